// round 16
// baseline (speedup 1.0000x reference)
#include <cuda_runtime.h>
#include <cstdint>

#define BB 4
#define HH 8
#define SS 2048
#define DD 512
#define DH 64
#define TOPK 10

// Scratch: Q,K transposed [bh][d][s] (d-major, for attn staging);
// K,V row-major [bh][s][d] (rescore / context read rows).
__device__ float g_Qt[BB*HH*DH*SS];
__device__ float g_Kt[BB*HH*DH*SS];
__device__ float g_K [BB*HH*SS*DH];
__device__ float g_V [BB*HH*SS*DH];

__device__ __forceinline__ float neg_inf() { return __int_as_float(0xff800000); }

__device__ __forceinline__ void cpa16(void* s, const void* g) {
    uint32_t sa = (uint32_t)__cvta_generic_to_shared(s);
    asm volatile("cp.async.cg.shared.global [%0], [%1], 16;" :: "r"(sa), "l"(g));
}
__device__ __forceinline__ void cpa_commit() {
    asm volatile("cp.async.commit_group;");
}
__device__ __forceinline__ void cpa_wait0() {
    asm volatile("cp.async.wait_group 0;");
}

// ---------------------------------------------------------------------------
// Kernel 1: Y = x @ W^T + b; Q,K transposed scatter, K also row-major,
// V row-major. Serial ascending-k FMA chain per output (bit-exact).
// Also zero-fills out_attn (hidden in the FMA shadow).
// ---------------------------------------------------------------------------
__global__ __launch_bounds__(256) void qkv_kernel(
    const float* __restrict__ x,
    const float* __restrict__ Wq, const float* __restrict__ bq,
    const float* __restrict__ Wk, const float* __restrict__ bk,
    const float* __restrict__ Wv, const float* __restrict__ bv,
    float* __restrict__ out_attn)
{
    const int which = blockIdx.z;
    const float* __restrict__ W    = (which == 0) ? Wq : (which == 1) ? Wk : Wv;
    const float* __restrict__ bias = (which == 0) ? bq : (which == 1) ? bk : bv;

    __shared__ float As[16][68];   // [k][m], padded
    __shared__ float Bs[16][68];   // [k][n], padded

    const int tid = threadIdx.x;
    const int tx  = tid & 15;       // 0..15 -> n
    const int ty  = tid >> 4;       // 0..15 -> m
    const int m0  = blockIdx.y * 64;
    const int n0  = blockIdx.x * 64;   // one head per n-tile (DH==64)

    const int lrow = tid >> 2;      // 0..63
    const int lk4  = tid & 3;       // 0..3

    // Zero-fill assignment: grid-stride over float4s of out_attn.
    const int  bid   = blockIdx.x + (blockIdx.y << 3) + (blockIdx.z << 10); // 0..3071
    const uint32_t gtid = tid + (bid << 8);            // 0..786431
    const uint32_t zstride = 3072u * 256u;             // total threads
    const uint32_t ztotal  = (uint32_t)((size_t)BB * HH * SS * SS / 4);  // 33554432
    float4* __restrict__ zdst = (float4*)out_attn;
    const float4 zf4 = make_float4(0.f, 0.f, 0.f, 0.f);

    float c[4][4];
    #pragma unroll
    for (int i = 0; i < 4; ++i)
        #pragma unroll
        for (int j = 0; j < 4; ++j) c[i][j] = 0.f;

    for (int kt = 0; kt < DD / 16; ++kt) {
        float4 av = *(const float4*)&x[(size_t)(m0 + lrow) * DD + kt * 16 + lk4 * 4];
        float4 bv4 = *(const float4*)&W[(size_t)(n0 + lrow) * DD + kt * 16 + lk4 * 4];
        __syncthreads();
        As[lk4 * 4 + 0][lrow] = av.x;
        As[lk4 * 4 + 1][lrow] = av.y;
        As[lk4 * 4 + 2][lrow] = av.z;
        As[lk4 * 4 + 3][lrow] = av.w;
        Bs[lk4 * 4 + 0][lrow] = bv4.x;
        Bs[lk4 * 4 + 1][lrow] = bv4.y;
        Bs[lk4 * 4 + 2][lrow] = bv4.z;
        Bs[lk4 * 4 + 3][lrow] = bv4.w;
        __syncthreads();

        // Two zero stores per tile, drained by the write buffer under the FMAs.
        {
            uint32_t i0 = gtid + (uint32_t)(kt * 2 + 0) * zstride;
            uint32_t i1 = gtid + (uint32_t)(kt * 2 + 1) * zstride;
            if (i0 < ztotal) zdst[i0] = zf4;
            if (i1 < ztotal) zdst[i1] = zf4;
        }

        // k ascending; each c[i][j] is one serial FMA chain over all 512 k.
        #pragma unroll
        for (int k = 0; k < 16; ++k) {
            float4 a  = *(const float4*)&As[k][ty * 4];
            float4 b4 = *(const float4*)&Bs[k][tx * 4];
            c[0][0] = fmaf(a.x, b4.x, c[0][0]); c[0][1] = fmaf(a.x, b4.y, c[0][1]);
            c[0][2] = fmaf(a.x, b4.z, c[0][2]); c[0][3] = fmaf(a.x, b4.w, c[0][3]);
            c[1][0] = fmaf(a.y, b4.x, c[1][0]); c[1][1] = fmaf(a.y, b4.y, c[1][1]);
            c[1][2] = fmaf(a.y, b4.z, c[1][2]); c[1][3] = fmaf(a.y, b4.w, c[1][3]);
            c[2][0] = fmaf(a.z, b4.x, c[2][0]); c[2][1] = fmaf(a.z, b4.y, c[2][1]);
            c[2][2] = fmaf(a.z, b4.z, c[2][2]); c[2][3] = fmaf(a.z, b4.w, c[2][3]);
            c[3][0] = fmaf(a.w, b4.x, c[3][0]); c[3][1] = fmaf(a.w, b4.y, c[3][1]);
            c[3][2] = fmaf(a.w, b4.z, c[3][2]); c[3][3] = fmaf(a.w, b4.w, c[3][3]);
        }
    }

    float4 biasv = *(const float4*)&bias[n0 + tx * 4];
    const int head = blockIdx.x;
    #pragma unroll
    for (int i = 0; i < 4; ++i) {
        int m  = m0 + ty * 4 + i;
        int b_ = m >> 11;        // m / 2048
        int s_ = m & 2047;
        float o0 = c[i][0] + biasv.x;
        float o1 = c[i][1] + biasv.y;
        float o2 = c[i][2] + biasv.z;
        float o3 = c[i][3] + biasv.w;
        if (which == 2) {
            float4 o; o.x = o0; o.y = o1; o.z = o2; o.w = o3;
            *(float4*)&g_V[(size_t)(((b_ * HH + head) * SS) + s_) * DH + tx * 4] = o;
        } else {
            float* dst = (which == 0) ? g_Qt : g_Kt;
            size_t base = ((size_t)(b_ * HH + head) * DH + tx * 4) * SS + s_;
            dst[base + 0 * SS] = o0;
            dst[base + 1 * SS] = o1;
            dst[base + 2 * SS] = o2;
            dst[base + 3 * SS] = o3;
            if (which == 1) {   // K also row-major for exact rescore
                float4 o; o.x = o0; o.y = o1; o.z = o2; o.w = o3;
                *(float4*)&g_K[(size_t)(((b_ * HH + head) * SS) + s_) * DH + tx * 4] = o;
            }
        }
    }
}

// Insert (v, idx) into a descending top-10 list, ascending-k call order,
// strict > (earlier/lower index wins ties).
#define INSERT10(TV, TI, V, IDX) do {                                   \
    if ((V) > TV[TOPK - 1]) {                                           \
        float _vs = (V); int _is = (IDX);                               \
        _Pragma("unroll")                                               \
        for (int _t = 0; _t < TOPK; ++_t) {                             \
            if (_vs > TV[_t]) {                                         \
                float _tv = TV[_t]; TV[_t] = _vs; _vs = _tv;            \
                int _ti2 = TI[_t]; TI[_t] = _is; _is = _ti2;            \
            }                                                           \
        }                                                               \
    }                                                                   \
} while (0)

// ---------------------------------------------------------------------------
// Kernel 2: tf32 tensor-core PREFILTER (scores scanned IN REGISTERS) +
// exact rescore. Per (b,h, 32-q-row tile): 128 threads (4 warps), warp patch
// 16q x 32k of a 32q x 64k tile. Each thread's MMA fragments cover 2 q-rows;
// it keeps TWO top-10 lists and scans its accumulators directly — no score
// smem roundtrip, ONE barrier per tile (double-buffered Bs + cp.async).
// Then: exact serial ascending-d FMA rescore of 8x10 candidates/row, merge
// (ties -> lower index), softmax, scatter, context. Bit-identical output.
// ---------------------------------------------------------------------------
__global__ __launch_bounds__(128, 4) void attn_kernel(
    float* __restrict__ out_ctx, float* __restrict__ out_attn)
{
    __shared__ float As[64 * 36];        // Q·0.125 [d][q] (exact fp32)
    __shared__ float Bsm[2 * 64 * 68];   // K [d][k], double buffer
    // Post-loop overlays (dead after the k-loop):
    float* cv  = Bsm;                    // 32 rows x 80 floats (exact rescored)
    int*   ci  = (int*)(Bsm + 2560);     // 32 rows x 80 ints
    float* pb  = As;                     // 32*10 floats (after rescore)
    int*   tix = (int*)(As + 320);       // 32*10 ints

    const int qt  = blockIdx.x;      // 0..63 (32 q-rows each)
    const int bh  = blockIdx.y;      // 0..31
    const int tid = threadIdx.x;     // 0..127
    // mma geometry
    const int lane  = tid & 31;
    const int g     = lane >> 2;     // groupID 0..7
    const int tig   = lane & 3;      // thread-in-group 0..3
    const int qb    = (tid >> 6) * 16;       // warp q base: 0 or 16
    const int kwarp = (tid >> 5) & 1;
    const int kb    = kwarp * 32;            // warp k base: 0 or 32
    const int slot  = kwarp * 4 + tig;       // 0..7 candidate slot per row
    const int r1    = qb + g;                // fragment row 1
    const int r2    = qb + g + 8;            // fragment row 2
    // epilogue geometry
    const int srow = tid >> 2;       // 0..31
    const int scg  = tid & 3;        // 0..3

    const float* __restrict__ Qt = g_Qt + (size_t)bh * DH * SS;
    const float* __restrict__ Kt = g_Kt + (size_t)bh * DH * SS;
    const float* __restrict__ Kr = g_K  + (size_t)bh * SS * DH;
    const float* __restrict__ Vb = g_V  + (size_t)bh * SS * DH;

    // Stage As = Q^T tile (64d x 32q), scaled by 1/8 (exact pow2).
    #pragma unroll
    for (int p = 0; p < 4; ++p) {
        int idx = p * 128 + tid;     // 0..511 float4s
        int d   = idx >> 3;
        int qf4 = idx & 7;
        float4 v = *(const float4*)&Qt[(size_t)d * SS + qt * 32 + qf4 * 4];
        v.x *= 0.125f; v.y *= 0.125f; v.z *= 0.125f; v.w *= 0.125f;
        *(float4*)&As[d * 36 + qf4 * 4] = v;
    }

    // Preload K tile 0 into buffer 0.
    #pragma unroll
    for (int p = 0; p < 8; ++p) {
        int idx = p * 128 + tid;     // 0..1023 float4s
        int d   = idx >> 4;
        int kf4 = idx & 15;
        cpa16(&Bsm[d * 68 + kf4 * 4], &Kt[(size_t)d * SS + kf4 * 4]);
    }
    cpa_commit();
    cpa_wait0();
    __syncthreads();                  // As + Bs(tile 0) ready

    float tv1[TOPK], tv2[TOPK];
    int   ti1[TOPK], ti2[TOPK];
    #pragma unroll
    for (int t = 0; t < TOPK; ++t) {
        tv1[t] = neg_inf(); ti1[t] = 0x7FFFFFFF;
        tv2[t] = neg_inf(); ti2[t] = 0x7FFFFFFF;
    }

    const int NT = SS / 64;           // 32 tiles
    for (int kt = 0; kt < NT; ++kt) {
        float* Bc = Bsm + (kt & 1) * 4352;
        float* Bn = Bsm + ((kt + 1) & 1) * 4352;

        // Prefetch tile kt+1 into the other buffer (reads of Bn finished at
        // the barrier ending tile kt-1). Covered by MMA + scan below.
        if (kt + 1 < NT) {
            #pragma unroll
            for (int p = 0; p < 8; ++p) {
                int idx = p * 128 + tid;
                int d   = idx >> 4;
                int kf4 = idx & 15;
                cpa16(&Bn[d * 68 + kf4 * 4],
                      &Kt[(size_t)d * SS + (kt + 1) * 64 + kf4 * 4]);
            }
            cpa_commit();
        }

        // Approx GEMM: 4 n-patches of m16n8, accumulated over 8 k-chunks.
        float c[4][4];
        #pragma unroll
        for (int p = 0; p < 4; ++p)
            #pragma unroll
            for (int j = 0; j < 4; ++j) c[p][j] = 0.f;

        #pragma unroll
        for (int kc = 0; kc < 8; ++kc) {
            const int d0 = kc * 8;
            float a0 = As[(d0 + tig)     * 36 + qb + g];
            float a1 = As[(d0 + tig)     * 36 + qb + g + 8];
            float a2 = As[(d0 + tig + 4) * 36 + qb + g];
            float a3 = As[(d0 + tig + 4) * 36 + qb + g + 8];
            #pragma unroll
            for (int p = 0; p < 4; ++p) {
                const int nb = kb + p * 8;
                float b0 = Bc[(d0 + tig)     * 68 + nb + g];
                float b1 = Bc[(d0 + tig + 4) * 68 + nb + g];
                asm volatile(
                    "mma.sync.aligned.m16n8k8.row.col.f32.tf32.tf32.f32 "
                    "{%0,%1,%2,%3}, {%4,%5,%6,%7}, {%8,%9}, {%0,%1,%2,%3};\n"
                    : "+f"(c[p][0]), "+f"(c[p][1]), "+f"(c[p][2]), "+f"(c[p][3])
                    : "r"(__float_as_uint(a0)), "r"(__float_as_uint(a1)),
                      "r"(__float_as_uint(a2)), "r"(__float_as_uint(a3)),
                      "r"(__float_as_uint(b0)), "r"(__float_as_uint(b1)));
            }
        }

        // Scan fragments in registers, ascending k within this thread.
        // c[p][0,1] -> row r1 cols k0,k0+1 ; c[p][2,3] -> row r2 same cols.
        #pragma unroll
        for (int p = 0; p < 4; ++p) {
            const int k0 = kt * 64 + kb + p * 8 + 2 * tig;
            float m1 = fmaxf(c[p][0], c[p][1]);
            if (m1 > tv1[TOPK - 1]) {
                INSERT10(tv1, ti1, c[p][0], k0);
                INSERT10(tv1, ti1, c[p][1], k0 + 1);
            }
            float m2 = fmaxf(c[p][2], c[p][3]);
            if (m2 > tv2[TOPK - 1]) {
                INSERT10(tv2, ti2, c[p][2], k0);
                INSERT10(tv2, ti2, c[p][3], k0 + 1);
            }
        }

        cpa_wait0();
        __syncthreads();              // next tile resident; Bc reads done
    }

    // Candidate indices into overlay (Bsm dead now).
    #pragma unroll
    for (int t = 0; t < TOPK; ++t) {
        ci[r1 * 80 + slot * TOPK + t] = ti1[t];
        ci[r2 * 80 + slot * TOPK + t] = ti2[t];
    }

    // EXACT rescore of this thread's 20 candidates: serial ascending-d FMA
    // chain with the same As operands as the exact GEMM; K rows from g_K.
    #pragma unroll
    for (int h = 0; h < 2; ++h) {
        const int r = h ? r2 : r1;
        const int* tsrc = h ? ti2 : ti1;
        #pragma unroll
        for (int t = 0; t < TOPK; ++t) {
            int kidx = tsrc[t];
            float acc = neg_inf();
            if (kidx < SS) {
                const float4* krow = (const float4*)(Kr + (size_t)kidx * DH);
                acc = 0.f;
                #pragma unroll
                for (int j = 0; j < 16; ++j) {
                    float4 kv = krow[j];
                    acc = fmaf(As[(j * 4 + 0) * 36 + r], kv.x, acc);
                    acc = fmaf(As[(j * 4 + 1) * 36 + r], kv.y, acc);
                    acc = fmaf(As[(j * 4 + 2) * 36 + r], kv.z, acc);
                    acc = fmaf(As[(j * 4 + 3) * 36 + r], kv.w, acc);
                }
            }
            cv[r * 80 + slot * TOPK + t] = acc;
        }
    }
    __syncthreads();

    // Merge 8 exact candidate lists per row; ties -> lower index (lax.top_k).
    if (tid < 32) {
        int base = tid * 80;
        for (int s = 0; s < TOPK; ++s) {
            float best = neg_inf(); int bi = 0x7FFFFFFF; int bp = 0;
            for (int p = 0; p < 80; ++p) {
                float v = cv[base + p]; int ii = ci[base + p];
                if (v > best || (v == best && ii < bi)) { best = v; bi = ii; bp = p; }
            }
            cv[base + bp] = neg_inf();
            pb[tid * TOPK + s] = best;
            tix[tid * TOPK + s] = bi;
        }
        float mx = pb[tid * TOPK];
        float pr[TOPK]; float Z = 0.f;
        #pragma unroll
        for (int s = 0; s < TOPK; ++s) {
            float e = expf(pb[tid * TOPK + s] - mx);
            pr[s] = e; Z += e;
        }
        #pragma unroll
        for (int s = 0; s < TOPK; ++s) pb[tid * TOPK + s] = pr[s] / Z;
    }
    __syncthreads();

    const int q = qt * 32 + srow;
    const size_t abase = ((size_t)bh * SS + q) * SS;
    for (int t = scg; t < TOPK; t += 4)
        out_attn[abase + tix[srow * TOPK + t]] = pb[srow * TOPK + t];

    // Context: 4 threads per row, 16 dh-columns each.
    float acc[16];
    #pragma unroll
    for (int j = 0; j < 16; ++j) acc[j] = 0.f;
    #pragma unroll
    for (int t = 0; t < TOPK; ++t) {
        float p = pb[srow * TOPK + t];
        const float* vr = &Vb[(size_t)tix[srow * TOPK + t] * DH + scg * 16];
        #pragma unroll
        for (int j4 = 0; j4 < 4; ++j4) {
            float4 v = *(const float4*)&vr[j4 * 4];
            acc[j4*4+0] = fmaf(p, v.x, acc[j4*4+0]);
            acc[j4*4+1] = fmaf(p, v.y, acc[j4*4+1]);
            acc[j4*4+2] = fmaf(p, v.z, acc[j4*4+2]);
            acc[j4*4+3] = fmaf(p, v.w, acc[j4*4+3]);
        }
    }
    const int b_ = bh >> 3, h_ = bh & 7;
    float* dst = out_ctx + ((size_t)(b_ * SS + q)) * DD + h_ * DH + scg * 16;
    #pragma unroll
    for (int j4 = 0; j4 < 4; ++j4) {
        float4 o;
        o.x = acc[j4*4+0]; o.y = acc[j4*4+1];
        o.z = acc[j4*4+2]; o.w = acc[j4*4+3];
        *(float4*)&dst[j4 * 4] = o;
    }
}

// ---------------------------------------------------------------------------
extern "C" void kernel_launch(void* const* d_in, const int* in_sizes, int n_in,
                              void* d_out, int out_size)
{
    const float* x  = (const float*)d_in[0];
    const float* Wq = (const float*)d_in[1];
    const float* bq = (const float*)d_in[2];
    const float* Wk = (const float*)d_in[3];
    const float* bk = (const float*)d_in[4];
    const float* Wv = (const float*)d_in[5];
    const float* bv = (const float*)d_in[6];

    float* out_ctx  = (float*)d_out;
    float* out_attn = out_ctx + (size_t)BB * SS * DD;

    // qkv also zero-fills out_attn (grid-stride, hidden in FMA shadow).
    dim3 g1(DD / 64, (BB * SS) / 64, 3);   // (8, 128, 3)
    qkv_kernel<<<g1, 256>>>(x, Wq, bq, Wk, bk, Wv, bv, out_attn);

    dim3 g2(SS / 32, BB * HH);             // (64, 32)
    attn_kernel<<<g2, 128>>>(out_ctx, out_attn);
}

// round 17
// speedup vs baseline: 1.4081x; 1.4081x over previous
#include <cuda_runtime.h>
#include <cstdint>

#define BB 4
#define HH 8
#define SS 2048
#define DD 512
#define DH 64
#define TOPK 10

// Scratch: Q transposed [bh][d][s] (d-major, for attn A staging);
// K,V row-major [bh][s][d] (B tiles, rescore, context).
__device__ float g_Qt[BB*HH*DH*SS];
__device__ float g_K [BB*HH*SS*DH];
__device__ float g_V [BB*HH*SS*DH];

__device__ __forceinline__ float neg_inf() { return __int_as_float(0xff800000); }

__device__ __forceinline__ void cpa16(void* s, const void* g) {
    uint32_t sa = (uint32_t)__cvta_generic_to_shared(s);
    asm volatile("cp.async.cg.shared.global [%0], [%1], 16;" :: "r"(sa), "l"(g));
}
__device__ __forceinline__ void cpa_commit() {
    asm volatile("cp.async.commit_group;");
}
__device__ __forceinline__ void cpa_wait0() {
    asm volatile("cp.async.wait_group 0;");
}

// ---------------------------------------------------------------------------
// Kernel 1: Y = x @ W^T + b; Q transposed scatter, K and V row-major
// (coalesced float4 only — no more scattered K stores). Serial ascending-k
// FMA chain per output (bit-exact). Also zero-fills out_attn (hidden in the
// FMA shadow).
// ---------------------------------------------------------------------------
__global__ __launch_bounds__(256) void qkv_kernel(
    const float* __restrict__ x,
    const float* __restrict__ Wq, const float* __restrict__ bq,
    const float* __restrict__ Wk, const float* __restrict__ bk,
    const float* __restrict__ Wv, const float* __restrict__ bv,
    float* __restrict__ out_attn)
{
    const int which = blockIdx.z;
    const float* __restrict__ W    = (which == 0) ? Wq : (which == 1) ? Wk : Wv;
    const float* __restrict__ bias = (which == 0) ? bq : (which == 1) ? bk : bv;

    __shared__ float As[16][68];   // [k][m], padded
    __shared__ float Bs[16][68];   // [k][n], padded

    const int tid = threadIdx.x;
    const int tx  = tid & 15;       // 0..15 -> n
    const int ty  = tid >> 4;       // 0..15 -> m
    const int m0  = blockIdx.y * 64;
    const int n0  = blockIdx.x * 64;   // one head per n-tile (DH==64)

    const int lrow = tid >> 2;      // 0..63
    const int lk4  = tid & 3;       // 0..3

    // Zero-fill assignment: grid-stride over float4s of out_attn.
    const int  bid   = blockIdx.x + (blockIdx.y << 3) + (blockIdx.z << 10); // 0..3071
    const uint32_t gtid = tid + (bid << 8);            // 0..786431
    const uint32_t zstride = 3072u * 256u;             // total threads
    const uint32_t ztotal  = (uint32_t)((size_t)BB * HH * SS * SS / 4);  // 33554432
    float4* __restrict__ zdst = (float4*)out_attn;
    const float4 zf4 = make_float4(0.f, 0.f, 0.f, 0.f);

    float c[4][4];
    #pragma unroll
    for (int i = 0; i < 4; ++i)
        #pragma unroll
        for (int j = 0; j < 4; ++j) c[i][j] = 0.f;

    for (int kt = 0; kt < DD / 16; ++kt) {
        float4 av = *(const float4*)&x[(size_t)(m0 + lrow) * DD + kt * 16 + lk4 * 4];
        float4 bv4 = *(const float4*)&W[(size_t)(n0 + lrow) * DD + kt * 16 + lk4 * 4];
        __syncthreads();
        As[lk4 * 4 + 0][lrow] = av.x;
        As[lk4 * 4 + 1][lrow] = av.y;
        As[lk4 * 4 + 2][lrow] = av.z;
        As[lk4 * 4 + 3][lrow] = av.w;
        Bs[lk4 * 4 + 0][lrow] = bv4.x;
        Bs[lk4 * 4 + 1][lrow] = bv4.y;
        Bs[lk4 * 4 + 2][lrow] = bv4.z;
        Bs[lk4 * 4 + 3][lrow] = bv4.w;
        __syncthreads();

        // Two zero stores per tile, drained by the write buffer under the FMAs.
        {
            uint32_t i0 = gtid + (uint32_t)(kt * 2 + 0) * zstride;
            uint32_t i1 = gtid + (uint32_t)(kt * 2 + 1) * zstride;
            if (i0 < ztotal) zdst[i0] = zf4;
            if (i1 < ztotal) zdst[i1] = zf4;
        }

        // k ascending; each c[i][j] is one serial FMA chain over all 512 k.
        #pragma unroll
        for (int k = 0; k < 16; ++k) {
            float4 a  = *(const float4*)&As[k][ty * 4];
            float4 b4 = *(const float4*)&Bs[k][tx * 4];
            c[0][0] = fmaf(a.x, b4.x, c[0][0]); c[0][1] = fmaf(a.x, b4.y, c[0][1]);
            c[0][2] = fmaf(a.x, b4.z, c[0][2]); c[0][3] = fmaf(a.x, b4.w, c[0][3]);
            c[1][0] = fmaf(a.y, b4.x, c[1][0]); c[1][1] = fmaf(a.y, b4.y, c[1][1]);
            c[1][2] = fmaf(a.y, b4.z, c[1][2]); c[1][3] = fmaf(a.y, b4.w, c[1][3]);
            c[2][0] = fmaf(a.z, b4.x, c[2][0]); c[2][1] = fmaf(a.z, b4.y, c[2][1]);
            c[2][2] = fmaf(a.z, b4.z, c[2][2]); c[2][3] = fmaf(a.z, b4.w, c[2][3]);
            c[3][0] = fmaf(a.w, b4.x, c[3][0]); c[3][1] = fmaf(a.w, b4.y, c[3][1]);
            c[3][2] = fmaf(a.w, b4.z, c[3][2]); c[3][3] = fmaf(a.w, b4.w, c[3][3]);
        }
    }

    float4 biasv = *(const float4*)&bias[n0 + tx * 4];
    const int head = blockIdx.x;
    #pragma unroll
    for (int i = 0; i < 4; ++i) {
        int m  = m0 + ty * 4 + i;
        int b_ = m >> 11;        // m / 2048
        int s_ = m & 2047;
        float o0 = c[i][0] + biasv.x;
        float o1 = c[i][1] + biasv.y;
        float o2 = c[i][2] + biasv.z;
        float o3 = c[i][3] + biasv.w;
        if (which == 0) {
            // Q: transposed scatter [bh][d][s] for the A-staging path.
            size_t base = ((size_t)(b_ * HH + head) * DH + tx * 4) * SS + s_;
            g_Qt[base + 0 * SS] = o0;
            g_Qt[base + 1 * SS] = o1;
            g_Qt[base + 2 * SS] = o2;
            g_Qt[base + 3 * SS] = o3;
        } else {
            // K, V: row-major coalesced float4 store.
            float* dst = (which == 1) ? g_K : g_V;
            float4 o; o.x = o0; o.y = o1; o.z = o2; o.w = o3;
            *(float4*)&dst[(size_t)(((b_ * HH + head) * SS) + s_) * DH + tx * 4] = o;
        }
    }
}

// ---------------------------------------------------------------------------
// Kernel 2 (R14 structure): tf32 tensor-core PREFILTER + exact rescore.
// Per (b,h, 32-q-row tile): 128 threads (4 warps). Approx scores for a
// 32q x 64k tile via mma.m16n8k8.tf32 (warp patch 16q x 32k). Bs tile is
// K-MAJOR ([k][d], stride 68) so it stages straight from row-major g_K;
// B-fragment loads are bank-verified conflict-free. Scan approx scores from
// smem -> per-thread top-10 indices; EXACT serial ascending-d FMA rescore of
// 40 candidates/row; merge (ties -> lower index); softmax; scatter; context.
// Output bit-identical to the exact kernel given candidate containment.
// ---------------------------------------------------------------------------
__global__ __launch_bounds__(128, 6) void attn_kernel(
    float* __restrict__ out_ctx, float* __restrict__ out_attn)
{
    __shared__ float As[64 * 36];        // Q·0.125  [d][q] (exact fp32)
    __shared__ float Bs[64 * 68];        // K        [k][d]  (k-major!)
    __shared__ float Sc[32 * 68];        // approx scores [q][k]
    // Post-loop overlays (regions dead after the last GEMM/scan):
    float* cv  = Bs;                     // 128*10 floats (exact rescored)
    int*   ci  = (int*)(Bs + 1280);      // 128*10 ints   (candidate indices)
    float* pb  = As;                     // 32*10 floats
    int*   tix = (int*)(As + 320);       // 32*10 ints

    const int qt  = blockIdx.x;      // 0..63 (32 q-rows each)
    const int bh  = blockIdx.y;      // 0..31
    const int tid = threadIdx.x;     // 0..127
    // mma geometry
    const int lane = tid & 31;
    const int g    = lane >> 2;      // groupID 0..7
    const int tig  = lane & 3;       // thread-in-group 0..3
    const int qb   = (tid >> 6) * 16;        // warp q base: 0 or 16
    const int kb   = ((tid >> 5) & 1) * 32;  // warp k base: 0 or 32
    // scan geometry
    const int srow = tid >> 2;       // 0..31 scan row
    const int scg  = tid & 3;        // 0..3  scan col group

    const float* __restrict__ Qt = g_Qt + (size_t)bh * DH * SS;
    const float* __restrict__ Kr = g_K  + (size_t)bh * SS * DH;
    const float* __restrict__ Vb = g_V  + (size_t)bh * SS * DH;

    // Stage As = Q^T tile (64d x 32q), scaled by 1/8 (exact pow2).
    #pragma unroll
    for (int p = 0; p < 4; ++p) {
        int idx = p * 128 + tid;     // 0..511 float4s
        int d   = idx >> 3;
        int qf4 = idx & 7;
        float4 v = *(const float4*)&Qt[(size_t)d * SS + qt * 32 + qf4 * 4];
        v.x *= 0.125f; v.y *= 0.125f; v.z *= 0.125f; v.w *= 0.125f;
        *(float4*)&As[d * 36 + qf4 * 4] = v;
    }

    // Preload K tile 0 via cp.async: 64 k-rows x 64 d (k-major, from g_K).
    #pragma unroll
    for (int p = 0; p < 8; ++p) {
        int idx = p * 128 + tid;     // 0..1023 float4s
        int k   = idx >> 4;
        int df4 = idx & 15;
        cpa16(&Bs[k * 68 + df4 * 4], &Kr[(size_t)k * DH + df4 * 4]);
    }
    cpa_commit();
    cpa_wait0();
    __syncthreads();                  // As + Bs(tile 0) ready

    float tv[TOPK];
    int   ti[TOPK];
    #pragma unroll
    for (int t = 0; t < TOPK; ++t) { tv[t] = neg_inf(); ti[t] = 0x7FFFFFFF; }

    for (int kt = 0; kt < SS / 64; ++kt) {
        // Approx GEMM: 4 n-patches of m16n8, accumulated over 8 k-chunks.
        float c[4][4];
        #pragma unroll
        for (int p = 0; p < 4; ++p)
            #pragma unroll
            for (int j = 0; j < 4; ++j) c[p][j] = 0.f;

        #pragma unroll
        for (int kc = 0; kc < 8; ++kc) {
            const int d0 = kc * 8;
            float a0 = As[(d0 + tig)     * 36 + qb + g];
            float a1 = As[(d0 + tig)     * 36 + qb + g + 8];
            float a2 = As[(d0 + tig + 4) * 36 + qb + g];
            float a3 = As[(d0 + tig + 4) * 36 + qb + g + 8];
            #pragma unroll
            for (int p = 0; p < 4; ++p) {
                const int nb = kb + p * 8;
                // B fragment from k-major tile: element (k=nb+g, d=d0+tig[+4]).
                float b0 = Bs[(nb + g) * 68 + d0 + tig];
                float b1 = Bs[(nb + g) * 68 + d0 + tig + 4];
                asm volatile(
                    "mma.sync.aligned.m16n8k8.row.col.f32.tf32.tf32.f32 "
                    "{%0,%1,%2,%3}, {%4,%5,%6,%7}, {%8,%9}, {%0,%1,%2,%3};\n"
                    : "+f"(c[p][0]), "+f"(c[p][1]), "+f"(c[p][2]), "+f"(c[p][3])
                    : "r"(__float_as_uint(a0)), "r"(__float_as_uint(a1)),
                      "r"(__float_as_uint(a2)), "r"(__float_as_uint(a3)),
                      "r"(__float_as_uint(b0)), "r"(__float_as_uint(b1)));
            }
        }
        // Dump approx scores (C frag: c0/c1 at cols 2*tig,+1; c2/c3 at q+8).
        #pragma unroll
        for (int p = 0; p < 4; ++p) {
            const int col = kb + p * 8 + 2 * tig;
            *(float2*)&Sc[(qb + g)     * 68 + col] = make_float2(c[p][0], c[p][1]);
            *(float2*)&Sc[(qb + g + 8) * 68 + col] = make_float2(c[p][2], c[p][3]);
        }
        __syncthreads();             // Sc ready; all reads of Bs done

        // Prefetch next K tile into Bs — overlaps the scan below.
        if (kt + 1 < SS / 64) {
            #pragma unroll
            for (int p = 0; p < 8; ++p) {
                int idx = p * 128 + tid;
                int k   = idx >> 4;
                int df4 = idx & 15;
                cpa16(&Bs[k * 68 + df4 * 4],
                      &Kr[(size_t)((kt + 1) * 64 + k) * DH + df4 * 4]);
            }
            cpa_commit();
        }

        // Scan (approx values): per-thread top-10 with max-of-4 fast path.
        #pragma unroll
        for (int j4 = 0; j4 < 4; ++j4) {
            float4 s = *(const float4*)&Sc[srow * 68 + scg * 16 + j4 * 4];
            float mx4 = fmaxf(fmaxf(s.x, s.y), fmaxf(s.z, s.w));
            if (mx4 > tv[TOPK - 1]) {
                int k0 = kt * 64 + scg * 16 + j4 * 4;
                float sv[4] = {s.x, s.y, s.z, s.w};
                #pragma unroll
                for (int e = 0; e < 4; ++e) {
                    if (sv[e] > tv[TOPK - 1]) {
                        float vs = sv[e]; int is = k0 + e;
                        #pragma unroll
                        for (int t = 0; t < TOPK; ++t) {
                            if (vs > tv[t]) {
                                float tmpv = tv[t]; tv[t] = vs; vs = tmpv;
                                int tmpi = ti[t]; ti[t] = is; is = tmpi;
                            }
                        }
                    }
                }
            }
        }
        cpa_wait0();
        __syncthreads();             // next Bs tile resident; scans done
    }

    // Candidate INDICES into overlay (Bs dead after final sync above).
    #pragma unroll
    for (int t = 0; t < TOPK; ++t)
        ci[tid * TOPK + t] = ti[t];
    __syncthreads();

    // EXACT rescore of this thread's 10 candidates: serial ascending-d FMA
    // chain with the same As operands as the exact GEMM; K row from g_K.
    {
        const int r = tid >> 2;       // this thread's q row
        #pragma unroll
        for (int t = 0; t < TOPK; ++t) {
            int kidx = ci[tid * TOPK + t];
            const float4* krow = (const float4*)(Kr + (size_t)kidx * DH);
            float acc = 0.f;
            #pragma unroll
            for (int j = 0; j < 16; ++j) {
                float4 kv = krow[j];
                acc = fmaf(As[(j * 4 + 0) * 36 + r], kv.x, acc);
                acc = fmaf(As[(j * 4 + 1) * 36 + r], kv.y, acc);
                acc = fmaf(As[(j * 4 + 2) * 36 + r], kv.z, acc);
                acc = fmaf(As[(j * 4 + 3) * 36 + r], kv.w, acc);
            }
            cv[tid * TOPK + t] = acc;
        }
    }
    __syncthreads();

    // Merge 4 exact candidate lists per row; ties -> lower index (lax.top_k).
    if (tid < 32) {
        int base = tid * 4 * TOPK;
        for (int s = 0; s < TOPK; ++s) {
            float best = neg_inf(); int bi = 0x7FFFFFFF; int bp = 0;
            for (int p = 0; p < 4 * TOPK; ++p) {
                float v = cv[base + p]; int ii = ci[base + p];
                if (v > best || (v == best && ii < bi)) { best = v; bi = ii; bp = p; }
            }
            cv[base + bp] = neg_inf();
            pb[tid * TOPK + s] = best;
            tix[tid * TOPK + s] = bi;
        }
        float mx = pb[tid * TOPK];
        float pr[TOPK]; float Z = 0.f;
        #pragma unroll
        for (int s = 0; s < TOPK; ++s) {
            float e = expf(pb[tid * TOPK + s] - mx);
            pr[s] = e; Z += e;
        }
        #pragma unroll
        for (int s = 0; s < TOPK; ++s) pb[tid * TOPK + s] = pr[s] / Z;
    }
    __syncthreads();

    const int q = qt * 32 + srow;
    const size_t abase = ((size_t)bh * SS + q) * SS;
    for (int t = scg; t < TOPK; t += 4)
        out_attn[abase + tix[srow * TOPK + t]] = pb[srow * TOPK + t];

    // Context: 4 threads per row, 16 dh-columns each.
    float acc[16];
    #pragma unroll
    for (int j = 0; j < 16; ++j) acc[j] = 0.f;
    #pragma unroll
    for (int t = 0; t < TOPK; ++t) {
        float p = pb[srow * TOPK + t];
        const float* vr = &Vb[(size_t)tix[srow * TOPK + t] * DH + scg * 16];
        #pragma unroll
        for (int j4 = 0; j4 < 4; ++j4) {
            float4 v = *(const float4*)&vr[j4 * 4];
            acc[j4*4+0] = fmaf(p, v.x, acc[j4*4+0]);
            acc[j4*4+1] = fmaf(p, v.y, acc[j4*4+1]);
            acc[j4*4+2] = fmaf(p, v.z, acc[j4*4+2]);
            acc[j4*4+3] = fmaf(p, v.w, acc[j4*4+3]);
        }
    }
    const int b_ = bh >> 3, h_ = bh & 7;
    float* dst = out_ctx + ((size_t)(b_ * SS + q)) * DD + h_ * DH + scg * 16;
    #pragma unroll
    for (int j4 = 0; j4 < 4; ++j4) {
        float4 o;
        o.x = acc[j4*4+0]; o.y = acc[j4*4+1];
        o.z = acc[j4*4+2]; o.w = acc[j4*4+3];
        *(float4*)&dst[j4 * 4] = o;
    }
}

// ---------------------------------------------------------------------------
extern "C" void kernel_launch(void* const* d_in, const int* in_sizes, int n_in,
                              void* d_out, int out_size)
{
    const float* x  = (const float*)d_in[0];
    const float* Wq = (const float*)d_in[1];
    const float* bq = (const float*)d_in[2];
    const float* Wk = (const float*)d_in[3];
    const float* bk = (const float*)d_in[4];
    const float* Wv = (const float*)d_in[5];
    const float* bv = (const float*)d_in[6];

    float* out_ctx  = (float*)d_out;
    float* out_attn = out_ctx + (size_t)BB * SS * DD;

    // qkv also zero-fills out_attn (grid-stride, hidden in FMA shadow).
    dim3 g1(DD / 64, (BB * SS) / 64, 3);   // (8, 128, 3)
    qkv_kernel<<<g1, 256>>>(x, Wq, bq, Wk, bk, Wv, bv, out_attn);

    dim3 g2(SS / 32, BB * HH);             // (64, 32)
    attn_kernel<<<g2, 128>>>(out_ctx, out_attn);
}